// round 9
// baseline (speedup 1.0000x reference)
#include <cuda_runtime.h>
#include <cuda_bf16.h>
#include <cstdint>
#include <cfloat>

// Problem constants
#define NN 65536
#define DD 128
#define MM 8
#define KK 256

#define BM      128
#define THREADS 512            // 16 warps: wr = wid&3 (32-row), wc = wid>>2 (64-col)

// bf16 tile row stride: 136 elems = 272B; 272 % 128 = 16 -> ldmatrix conflict-free
#define TSTR 136
#define ROWB 272

// smem layout (byte offsets)
#define SM_CBH   0                       // 256*272 = 69632
#define SM_CBL   69632                   // 69632
#define SM_RBH   139264                  // 128*272 = 34816
#define SM_RBL   174080                  // 34816
#define SM_CSQ   208896                  // 1024
#define SM_RSS   209920                  // 512
#define SM_MIN1  210432                  // 128*4*8 = 4096
#define SM_MIN2  214528                  // 4096
#define SM_BESTK 218624                  // 128*8 = 1024
#define SM_NEED  219648                  // 128*4 = 512
#define SM_BYTES 220160

// margin: 12x the ~3e-5 hi/lo screen error bound (same safety ratio validated at bf16)
#define MARG_COEF 4e-4f

__device__ float g_csq[MM][KK];
__device__ float g_cmax[MM];

__device__ __forceinline__ uint32_t ford(float f) {
    uint32_t u = __float_as_uint(f);
    return (u & 0x80000000u) ? ~u : (u | 0x80000000u);
}
__device__ __forceinline__ float unford(uint32_t e) {
    return __uint_as_float((e & 0x80000000u) ? (e & 0x7fffffffu) : ~e);
}
__device__ __forceinline__ uint32_t smem_u32(const void* p) {
    uint32_t a;
    asm("{ .reg .u64 t; cvta.to.shared.u64 t, %1; cvt.u32.u64 %0, t; }" : "=r"(a) : "l"(p));
    return a;
}
__device__ __forceinline__ void ldm_x4(uint32_t& r0, uint32_t& r1, uint32_t& r2,
                                       uint32_t& r3, uint32_t addr) {
    asm volatile("ldmatrix.sync.aligned.m8n8.x4.shared.b16 {%0,%1,%2,%3}, [%4];"
                 : "=r"(r0), "=r"(r1), "=r"(r2), "=r"(r3) : "r"(addr));
}
__device__ __forceinline__ void mma_bf16(float& c0, float& c1, float& c2, float& c3,
                                         uint32_t a0, uint32_t a1, uint32_t a2, uint32_t a3,
                                         uint32_t b0, uint32_t b1) {
    asm volatile("mma.sync.aligned.m16n8k16.row.col.f32.bf16.bf16.f32 "
                 "{%0,%1,%2,%3}, {%4,%5,%6,%7}, {%8,%9}, {%0,%1,%2,%3};"
                 : "+f"(c0), "+f"(c1), "+f"(c2), "+f"(c3)
                 : "r"(a0), "r"(a1), "r"(a2), "r"(a3), "r"(b0), "r"(b1));
}
// hi/lo bf16 split: v = hi + lo + O(2^-18 v); (v - hi) exact by Sterbenz
__device__ __forceinline__ void split2(float v0, float v1, uint32_t& hi, uint32_t& lo) {
    __nv_bfloat16 h0 = __float2bfloat16(v0), h1 = __float2bfloat16(v1);
    float l0 = v0 - __bfloat162float(h0), l1 = v1 - __bfloat162float(h1);
    __nv_bfloat162 hp = __nv_bfloat162(h0, h1);
    __nv_bfloat162 lp = __nv_bfloat162(__float2bfloat16(l0), __float2bfloat16(l1));
    hi = *(uint32_t*)&hp;
    lo = *(uint32_t*)&lp;
}
// (best,second) merge helpers
__device__ __forceinline__ void upd2(unsigned long long& b1, unsigned long long& b2,
                                     unsigned long long k) {
    if (k < b1) { b2 = b1; b1 = k; }
    else if (k < b2) b2 = k;
}
__device__ __forceinline__ void mrg2(unsigned long long& b1, unsigned long long& b2,
                                     unsigned long long o1, unsigned long long o2) {
    if (o1 < b1) { b2 = (b1 < o2) ? b1 : o2; b1 = o1; }
    else         { b2 = (b2 < o1) ? b2 : o1; }
}

__global__ void csq_prep_kernel(const float* __restrict__ cb) {
    int st = blockIdx.x;
    int k  = threadIdx.x;                  // 256 threads
    const float* row = cb + ((size_t)st * KK + k) * DD;
    float s = 0.f;
    for (int d = 0; d < DD; ++d) { float v = row[d]; s = fmaf(v, v, s); }
    g_csq[st][k] = s;
    __shared__ float red[KK];
    red[k] = s;
    __syncthreads();
    for (int off = 128; off > 0; off >>= 1) {
        if (k < off) red[k] = fmaxf(red[k], red[k + off]);
        __syncthreads();
    }
    if (k == 0) g_cmax[st] = sqrtf(red[0]);
}

__global__ __launch_bounds__(THREADS, 1)
void rq_stage_kernel(const float* __restrict__ x,
                     const float* __restrict__ C,       // stage codebook (K, D) fp32
                     const float* __restrict__ prev,    // side[stage-1] or null
                     float* __restrict__ codes,
                     float* __restrict__ sideStage,
                     float* __restrict__ xrecon,
                     int stage, int last)
{
    extern __shared__ char smem[];
    const uint32_t sbase = smem_u32(smem);
    float* csq = (float*)(smem + SM_CSQ);
    float* rss = (float*)(smem + SM_RSS);
    unsigned long long* min1  = (unsigned long long*)(smem + SM_MIN1);
    unsigned long long* min2  = (unsigned long long*)(smem + SM_MIN2);
    unsigned long long* bestk = (unsigned long long*)(smem + SM_BESTK);
    int* need = (int*)(smem + SM_NEED);

    const int tid  = threadIdx.x;
    const int wid  = tid >> 5;
    const int lane = tid & 31;
    const int rowBase = blockIdx.x * BM;

    // ---- codebook -> bf16 hi/lo smem tiles ----
    #pragma unroll 1
    for (int j = 0; j < (KK * DD / 2) / THREADS; ++j) {   // 32 pairs/thread
        int idx2 = tid + j * THREADS;
        int k = idx2 >> 6, dp = idx2 & 63;
        float2 v = *(const float2*)(C + (size_t)k * DD + dp * 2);
        uint32_t hi, lo;
        split2(v.x, v.y, hi, lo);
        *(uint32_t*)(smem + SM_CBH + k * ROWB + dp * 4) = hi;
        *(uint32_t*)(smem + SM_CBL + k * ROWB + dp * 4) = lo;
    }
    if (tid < KK) csq[tid] = g_csq[stage][tid];

    // ---- residual -> bf16 hi/lo tiles + exact fp32 rss ----
    {
        int r  = tid >> 2;
        int c0 = (tid & 3) * 32;
        const float* xrow = x + (size_t)(rowBase + r) * DD + c0;
        const float* prow = prev ? prev + (size_t)(rowBase + r) * DD + c0 : nullptr;
        float part = 0.f;
        #pragma unroll 1
        for (int j = 0; j < 32; j += 4) {
            float4 xv = *(const float4*)(xrow + j);
            float4 pv = prow ? *(const float4*)(prow + j) : make_float4(0.f,0.f,0.f,0.f);
            float r0 = xv.x - pv.x, r1 = xv.y - pv.y;
            float r2 = xv.z - pv.z, r3 = xv.w - pv.w;
            uint32_t hi, lo;
            split2(r0, r1, hi, lo);
            *(uint32_t*)(smem + SM_RBH + r * ROWB + (c0 + j) * 2) = hi;
            *(uint32_t*)(smem + SM_RBL + r * ROWB + (c0 + j) * 2) = lo;
            split2(r2, r3, hi, lo);
            *(uint32_t*)(smem + SM_RBH + r * ROWB + (c0 + j + 2) * 2) = hi;
            *(uint32_t*)(smem + SM_RBL + r * ROWB + (c0 + j + 2) * 2) = lo;
            part = fmaf(r0, r0, part); part = fmaf(r1, r1, part);
            part = fmaf(r2, r2, part); part = fmaf(r3, r3, part);
        }
        part += __shfl_xor_sync(0xffffffffu, part, 1);
        part += __shfl_xor_sync(0xffffffffu, part, 2);
        if ((tid & 3) == 0) rss[r] = part;
    }
    __syncthreads();

    const int wr = wid & 3;
    const int wc = wid >> 2;
    const int m_base  = wr * 32;
    const int n_base0 = wc * 64;
    const int qr = lane >> 2;
    const int qc = (lane & 3) * 2;

    // ldmatrix lane address offsets (bytes within a tile)
    const uint32_t aOff = (uint32_t)(((lane & 7) + ((lane >> 3) & 1) * 8 + m_base) * ROWB
                                     + ((lane >> 4) & 1) * 16);
    const uint32_t bOff = (uint32_t)(((lane & 7) + ((lane >> 4) & 1) * 8) * ROWB
                                     + ((lane >> 3) & 1) * 16);
    const uint32_t rbh = sbase + SM_RBH, rbl = sbase + SM_RBL;
    const uint32_t cbh = sbase + SM_CBH, cbl = sbase + SM_CBL;

    unsigned long long bk1[4], bk2[4];
    #pragma unroll
    for (int i = 0; i < 4; ++i) { bk1[i] = ~0ull; bk2[i] = ~0ull; }

    #pragma unroll 1
    for (int ch = 0; ch < 4; ++ch) {
        const int n_base = n_base0 + ch * 16;
        const uint32_t bCh = bOff + (uint32_t)n_base * ROWB;
        float acc[2][2][4];
        #pragma unroll
        for (int mt = 0; mt < 2; ++mt)
            #pragma unroll
            for (int nt = 0; nt < 2; ++nt)
                #pragma unroll
                for (int c = 0; c < 4; ++c) acc[mt][nt][c] = 0.f;

        // 3 passes into the same accumulators: hi*hi + hi*lo + lo*hi
        #pragma unroll 1
        for (int pass = 0; pass < 3; ++pass) {
            const uint32_t at = (pass == 2) ? rbl : rbh;
            const uint32_t bt = (pass == 1) ? cbl : cbh;
            #pragma unroll 2
            for (int ks = 0; ks < 8; ++ks) {
                const uint32_t k2 = (uint32_t)ks * 32;   // 16 bf16 = 32 bytes
                uint32_t a0[4], a1[4], b[4];
                ldm_x4(a0[0], a0[1], a0[2], a0[3], at + aOff + k2);
                ldm_x4(a1[0], a1[1], a1[2], a1[3], at + aOff + k2 + 16 * ROWB);
                ldm_x4(b[0],  b[1],  b[2],  b[3],  bt + bCh + k2);
                mma_bf16(acc[0][0][0], acc[0][0][1], acc[0][0][2], acc[0][0][3],
                         a0[0], a0[1], a0[2], a0[3], b[0], b[1]);
                mma_bf16(acc[0][1][0], acc[0][1][1], acc[0][1][2], acc[0][1][3],
                         a0[0], a0[1], a0[2], a0[3], b[2], b[3]);
                mma_bf16(acc[1][0][0], acc[1][0][1], acc[1][0][2], acc[1][0][3],
                         a1[0], a1[1], a1[2], a1[3], b[0], b[1]);
                mma_bf16(acc[1][1][0], acc[1][1][1], acc[1][1][2], acc[1][1][3],
                         a1[0], a1[1], a1[2], a1[3], b[2], b[3]);
            }
        }
        // fold chunk into (best, second) keys per row-slot
        #pragma unroll
        for (int mt = 0; mt < 2; ++mt)
            #pragma unroll
            for (int h = 0; h < 2; ++h) {
                int row = m_base + mt * 16 + h * 8 + qr;
                float rv = rss[row];
                int sl = mt * 2 + h;
                #pragma unroll
                for (int nt = 0; nt < 2; ++nt)
                    #pragma unroll
                    for (int p = 0; p < 2; ++p) {
                        int k = n_base + nt * 8 + qc + p;
                        float d2 = __fadd_rn(
                            __fadd_rn(rv, __fmul_rn(-2.f, acc[mt][nt][h * 2 + p])), csq[k]);
                        upd2(bk1[sl], bk2[sl],
                             ((unsigned long long)ford(d2) << 32) | (unsigned)k);
                    }
            }
    }
    // quad-reduce (lanes of same row), publish per-(row, wc) best/second
    #pragma unroll
    for (int i = 0; i < 4; ++i) {
        unsigned long long b1 = bk1[i], b2 = bk2[i];
        mrg2(b1, b2, __shfl_xor_sync(0xffffffffu, b1, 1), __shfl_xor_sync(0xffffffffu, b2, 1));
        mrg2(b1, b2, __shfl_xor_sync(0xffffffffu, b1, 2), __shfl_xor_sync(0xffffffffu, b2, 2));
        int row = m_base + (i >> 1) * 16 + (i & 1) * 8 + qr;
        if ((lane & 3) == 0) { min1[row * 4 + wc] = b1; min2[row * 4 + wc] = b2; }
    }
    __syncthreads();

    if (tid < BM) {
        unsigned long long b1 = min1[tid * 4], b2 = min2[tid * 4];
        mrg2(b1, b2, min1[tid * 4 + 1], min2[tid * 4 + 1]);
        mrg2(b1, b2, min1[tid * 4 + 2], min2[tid * 4 + 2]);
        mrg2(b1, b2, min1[tid * 4 + 3], min2[tid * 4 + 3]);
        float amin = unford((uint32_t)(b1 >> 32));
        float d2nd = unford((uint32_t)(b2 >> 32));
        float cutv = amin + MARG_COEF * sqrtf(rss[tid]) * g_cmax[stage];
        bestk[tid] = b1;
        need[tid]  = (d2nd <= cutv) ? 1 : 0;
    }
    __syncthreads();

    // ---- rescue: exact full 256-scan for ambiguous rows (identical chain semantics) ----
    #pragma unroll 1
    for (int rr = 0; rr < 8; ++rr) {
        int lrow = wid * 8 + rr;
        if (!need[lrow]) continue;                      // warp-uniform
        int n = rowBase + lrow;
        const float4* xr = (const float4*)(x + (size_t)n * DD);
        const float4* pr = prev ? (const float4*)(prev + (size_t)n * DD) : nullptr;
        float rv = rss[lrow];
        unsigned long long bw = ~0ull;
        #pragma unroll 1
        for (int c = 0; c < 8; ++c) {
            int k = lane + 32 * c;
            const float4* cr = (const float4*)(C + (size_t)k * DD);
            float a = 0.f;
            #pragma unroll 1
            for (int c2 = 0; c2 < 32; ++c2) {           // exact: d-ascending fmaf chain
                float4 xv = __ldg(xr + c2);
                float4 pv = pr ? __ldg(pr + c2) : make_float4(0.f, 0.f, 0.f, 0.f);
                float4 cv = __ldg(cr + c2);
                a = fmaf(xv.x - pv.x, cv.x, a);
                a = fmaf(xv.y - pv.y, cv.y, a);
                a = fmaf(xv.z - pv.z, cv.z, a);
                a = fmaf(xv.w - pv.w, cv.w, a);
            }
            float d2e = __fadd_rn(__fadd_rn(rv, __fmul_rn(-2.0f, a)), csq[k]);
            unsigned long long pk = ((unsigned long long)ford(d2e) << 32) | (unsigned)k;
            if (pk < bw) bw = pk;
        }
        #pragma unroll
        for (int off = 16; off > 0; off >>= 1) {
            unsigned long long o = __shfl_xor_sync(0xffffffffu, bw, off);
            if (o < bw) bw = o;
        }
        if (lane == 0) bestk[lrow] = bw;
    }
    __syncwarp();

    // ---- outputs: one-hot codes + recon (bit-exact recurrence), float4 stores ----
    #pragma unroll 1
    for (int rr = 0; rr < 8; ++rr) {
        int lrow = wid * 8 + rr;
        int n    = rowBase + lrow;
        int bidx = (int)(bestk[lrow] & 0xffffffffull);

        float4* crow = (float4*)(codes + (size_t)n * (MM * KK) + (size_t)stage * KK);
        #pragma unroll
        for (int t = 0; t < 2; ++t) {
            int j  = lane + 32 * t;
            int k0 = j * 4;
            float4 v;
            v.x = (k0     == bidx) ? 1.0f : 0.0f;
            v.y = (k0 + 1 == bidx) ? 1.0f : 0.0f;
            v.z = (k0 + 2 == bidx) ? 1.0f : 0.0f;
            v.w = (k0 + 3 == bidx) ? 1.0f : 0.0f;
            crow[j] = v;
        }
        float4 cv = __ldg((const float4*)(C + (size_t)bidx * DD) + lane);
        float4 pp = prev ? __ldg((const float4*)(prev + (size_t)n * DD) + lane)
                         : make_float4(0.f, 0.f, 0.f, 0.f);
        float4 v;
        v.x = __fadd_rn(pp.x, cv.x);
        v.y = __fadd_rn(pp.y, cv.y);
        v.z = __fadd_rn(pp.z, cv.z);
        v.w = __fadd_rn(pp.w, cv.w);
        ((float4*)(sideStage + (size_t)n * DD))[lane] = v;
        if (last) ((float4*)(xrecon + (size_t)n * DD))[lane] = v;
    }
}

extern "C" void kernel_launch(void* const* d_in, const int* in_sizes, int n_in,
                              void* d_out, int out_size)
{
    (void)in_sizes; (void)n_in; (void)out_size;
    const float* x  = (const float*)d_in[0];            // (N, D)
    const float* cb = (const float*)d_in[1];            // (M, K, D)

    float* out    = (float*)d_out;
    float* xrecon = out;                                // (N, D)
    float* codes  = out + (size_t)NN * DD;              // (N, M, K)
    float* side   = codes + (size_t)NN * MM * KK;       // (M, N, D)

    cudaFuncSetAttribute(rq_stage_kernel,
                         cudaFuncAttributeMaxDynamicSharedMemorySize, SM_BYTES);

    csq_prep_kernel<<<MM, KK>>>(cb);

    const int grid = NN / BM;   // 512
    for (int i = 0; i < MM; ++i) {
        const float* prev = (i == 0) ? nullptr : (side + (size_t)(i - 1) * NN * DD);
        rq_stage_kernel<<<grid, THREADS, SM_BYTES>>>(
            x, cb + (size_t)i * KK * DD, prev, codes,
            side + (size_t)i * NN * DD, xrecon, i, i == MM - 1);
    }
}

// round 11
// speedup vs baseline: 1.2170x; 1.2170x over previous
#include <cuda_runtime.h>
#include <cuda_fp16.h>
#include <cstdint>
#include <cfloat>

// Problem constants
#define NN 65536
#define DD 128
#define MM 8
#define KK 256

#define BM      128
#define THREADS 256            // 8 warps: wr = wid&3 (32-row group), wc = wid>>2 (128-col strip)

// fp16 tile row stride: 136 elems = 272B; 272 % 128 = 16 -> ldmatrix conflict-free
#define ROWB 272

// smem layout (byte offsets)
#define SM_CB    0                       // 256*272 = 69632
#define SM_RB    69632                   // 128*272 = 34816
#define SM_CSQ   104448                  // 1024
#define SM_RSS   105472                  // 512
#define SM_MIN1  105984                  // 128*2*8 = 2048
#define SM_MIN2  108032                  // 2048
#define SM_BESTK 110080                  // 128*8 = 1024
#define SM_NEED  111104                  // 128*4 = 512
#define SM_BYTES 111616                  // 109.0 KB -> 2 CTAs/SM

__device__ float g_csq[MM][KK];
__device__ float g_cmax[MM];

__device__ __forceinline__ uint32_t ford(float f) {
    uint32_t u = __float_as_uint(f);
    return (u & 0x80000000u) ? ~u : (u | 0x80000000u);
}
__device__ __forceinline__ float unford(uint32_t e) {
    return __uint_as_float((e & 0x80000000u) ? (e & 0x7fffffffu) : ~e);
}
__device__ __forceinline__ uint32_t smem_u32(const void* p) {
    uint32_t a;
    asm("{ .reg .u64 t; cvta.to.shared.u64 t, %1; cvt.u32.u64 %0, t; }" : "=r"(a) : "l"(p));
    return a;
}
__device__ __forceinline__ void ldm_x4(uint32_t& r0, uint32_t& r1, uint32_t& r2,
                                       uint32_t& r3, uint32_t addr) {
    asm volatile("ldmatrix.sync.aligned.m8n8.x4.shared.b16 {%0,%1,%2,%3}, [%4];"
                 : "=r"(r0), "=r"(r1), "=r"(r2), "=r"(r3) : "r"(addr));
}
__device__ __forceinline__ void mma_f16(float& c0, float& c1, float& c2, float& c3,
                                        uint32_t a0, uint32_t a1, uint32_t a2, uint32_t a3,
                                        uint32_t b0, uint32_t b1) {
    asm volatile("mma.sync.aligned.m16n8k16.row.col.f32.f16.f16.f32 "
                 "{%0,%1,%2,%3}, {%4,%5,%6,%7}, {%8,%9}, {%0,%1,%2,%3};"
                 : "+f"(c0), "+f"(c1), "+f"(c2), "+f"(c3)
                 : "r"(a0), "r"(a1), "r"(a2), "r"(a3), "r"(b0), "r"(b1));
}
__device__ __forceinline__ void upd2(unsigned long long& b1, unsigned long long& b2,
                                     unsigned long long k) {
    if (k < b1) { b2 = b1; b1 = k; }
    else if (k < b2) b2 = k;
}
__device__ __forceinline__ void mrg2(unsigned long long& b1, unsigned long long& b2,
                                     unsigned long long o1, unsigned long long o2) {
    if (o1 < b1) { b2 = (b1 < o2) ? b1 : o2; b1 = o1; }
    else         { b2 = (b2 < o1) ? b2 : o1; }
}

__global__ void csq_prep_kernel(const float* __restrict__ cb) {
    int st = blockIdx.x;
    int k  = threadIdx.x;                  // 256 threads
    const float* row = cb + ((size_t)st * KK + k) * DD;
    float s = 0.f;
    for (int d = 0; d < DD; ++d) { float v = row[d]; s = fmaf(v, v, s); }
    g_csq[st][k] = s;
    __shared__ float red[KK];
    red[k] = s;
    __syncthreads();
    for (int off = 128; off > 0; off >>= 1) {
        if (k < off) red[k] = fmaxf(red[k], red[k + off]);
        __syncthreads();
    }
    if (k == 0) g_cmax[st] = sqrtf(red[0]);
}

__global__ __launch_bounds__(THREADS, 2)
void rq_stage_kernel(const float* __restrict__ x,
                     const float* __restrict__ C,       // stage codebook (K, D) fp32
                     const float* __restrict__ prev,    // side[stage-1] or null
                     float* __restrict__ codes,
                     float* __restrict__ sideStage,
                     float* __restrict__ xrecon,
                     int stage, int last)
{
    extern __shared__ char smem[];
    const uint32_t sbase = smem_u32(smem);
    float* csq = (float*)(smem + SM_CSQ);
    float* rss = (float*)(smem + SM_RSS);
    unsigned long long* min1  = (unsigned long long*)(smem + SM_MIN1);
    unsigned long long* min2  = (unsigned long long*)(smem + SM_MIN2);
    unsigned long long* bestk = (unsigned long long*)(smem + SM_BESTK);
    int* need = (int*)(smem + SM_NEED);

    const int tid  = threadIdx.x;
    const int wid  = tid >> 5;
    const int lane = tid & 31;
    const int rowBase = blockIdx.x * BM;

    // ---- codebook fp32 -> fp16 smem tile (float4 loads for MLP) ----
    #pragma unroll 4
    for (int j = 0; j < (KK * DD / 4) / THREADS; ++j) {   // 32 float4s/thread
        int idx4 = tid + j * THREADS;
        int k = idx4 >> 5, dq = idx4 & 31;                // 32 float4 per row
        float4 v = *(const float4*)(C + (size_t)k * DD + dq * 4);
        __half2 h0 = __floats2half2_rn(v.x, v.y);
        __half2 h1 = __floats2half2_rn(v.z, v.w);
        uint2 pk = make_uint2(*(uint32_t*)&h0, *(uint32_t*)&h1);
        *(uint2*)(smem + SM_CB + k * ROWB + dq * 8) = pk;
    }
    if (tid < KK) csq[tid] = g_csq[stage][tid];

    // ---- residual -> fp16 tile + exact fp32 rss ----
    {
        int r  = tid >> 1;
        int c0 = (tid & 1) * 64;
        const float* xrow = x + (size_t)(rowBase + r) * DD + c0;
        const float* prow = prev ? prev + (size_t)(rowBase + r) * DD + c0 : nullptr;
        float part = 0.f;
        #pragma unroll 4
        for (int j = 0; j < 64; j += 4) {
            float4 xv = *(const float4*)(xrow + j);
            float4 pv = prow ? *(const float4*)(prow + j) : make_float4(0.f,0.f,0.f,0.f);
            float r0 = xv.x - pv.x, r1 = xv.y - pv.y;
            float r2 = xv.z - pv.z, r3 = xv.w - pv.w;
            __half2 h0 = __floats2half2_rn(r0, r1);
            __half2 h1 = __floats2half2_rn(r2, r3);
            uint2 pk = make_uint2(*(uint32_t*)&h0, *(uint32_t*)&h1);
            *(uint2*)(smem + SM_RB + r * ROWB + (c0 + j) * 2) = pk;
            part = fmaf(r0, r0, part); part = fmaf(r1, r1, part);
            part = fmaf(r2, r2, part); part = fmaf(r3, r3, part);
        }
        part += __shfl_xor_sync(0xffffffffu, part, 1);
        if ((tid & 1) == 0) rss[r] = part;
    }
    __syncthreads();

    const int wr = wid & 3;
    const int wc = wid >> 2;                // 0..1: 128-col strip
    const int m_base  = wr * 32;
    const int n_base0 = wc * 128;
    const int qr = lane >> 2;
    const int qc = (lane & 3) * 2;

    // ldmatrix lane address offsets (bytes within a tile)
    const uint32_t aOff = (uint32_t)(((lane & 7) + ((lane >> 3) & 1) * 8 + m_base) * ROWB
                                     + ((lane >> 4) & 1) * 16);
    const uint32_t bOff = (uint32_t)(((lane & 7) + ((lane >> 4) & 1) * 8) * ROWB
                                     + ((lane >> 3) & 1) * 16);
    const uint32_t rbT = sbase + SM_RB, cbT = sbase + SM_CB;

    unsigned long long bk1[4], bk2[4];
    #pragma unroll
    for (int i = 0; i < 4; ++i) { bk1[i] = ~0ull; bk2[i] = ~0ull; }

    // ---- single fp16 GEMM pass, 16-col chunks; fold (best,second) per row-slot ----
    #pragma unroll 1
    for (int ch = 0; ch < 8; ++ch) {
        const int n_base = n_base0 + ch * 16;
        const uint32_t bCh = bOff + (uint32_t)n_base * ROWB;
        float acc[2][2][4];
        #pragma unroll
        for (int mt = 0; mt < 2; ++mt)
            #pragma unroll
            for (int nt = 0; nt < 2; ++nt)
                #pragma unroll
                for (int c = 0; c < 4; ++c) acc[mt][nt][c] = 0.f;

        #pragma unroll 2
        for (int ks = 0; ks < 8; ++ks) {
            const uint32_t k2 = (uint32_t)ks * 32;   // 16 fp16 = 32 bytes
            uint32_t a0[4], a1[4], b[4];
            ldm_x4(a0[0], a0[1], a0[2], a0[3], rbT + aOff + k2);
            ldm_x4(a1[0], a1[1], a1[2], a1[3], rbT + aOff + k2 + 16 * ROWB);
            ldm_x4(b[0],  b[1],  b[2],  b[3],  cbT + bCh + k2);
            mma_f16(acc[0][0][0], acc[0][0][1], acc[0][0][2], acc[0][0][3],
                    a0[0], a0[1], a0[2], a0[3], b[0], b[1]);
            mma_f16(acc[0][1][0], acc[0][1][1], acc[0][1][2], acc[0][1][3],
                    a0[0], a0[1], a0[2], a0[3], b[2], b[3]);
            mma_f16(acc[1][0][0], acc[1][0][1], acc[1][0][2], acc[1][0][3],
                    a1[0], a1[1], a1[2], a1[3], b[0], b[1]);
            mma_f16(acc[1][1][0], acc[1][1][1], acc[1][1][2], acc[1][1][3],
                    a1[0], a1[1], a1[2], a1[3], b[2], b[3]);
        }
        #pragma unroll
        for (int mt = 0; mt < 2; ++mt)
            #pragma unroll
            for (int h = 0; h < 2; ++h) {
                int row = m_base + mt * 16 + h * 8 + qr;
                float rv = rss[row];
                int sl = mt * 2 + h;
                #pragma unroll
                for (int nt = 0; nt < 2; ++nt)
                    #pragma unroll
                    for (int p = 0; p < 2; ++p) {
                        int k = n_base + nt * 8 + qc + p;
                        float d2 = __fadd_rn(
                            __fadd_rn(rv, __fmul_rn(-2.f, acc[mt][nt][h * 2 + p])), csq[k]);
                        upd2(bk1[sl], bk2[sl],
                             ((unsigned long long)ford(d2) << 32) | (unsigned)k);
                    }
            }
    }
    // quad-reduce, publish per-(row, strip) best/second
    #pragma unroll
    for (int i = 0; i < 4; ++i) {
        unsigned long long b1 = bk1[i], b2 = bk2[i];
        mrg2(b1, b2, __shfl_xor_sync(0xffffffffu, b1, 1), __shfl_xor_sync(0xffffffffu, b2, 1));
        mrg2(b1, b2, __shfl_xor_sync(0xffffffffu, b1, 2), __shfl_xor_sync(0xffffffffu, b2, 2));
        int row = m_base + (i >> 1) * 16 + (i & 1) * 8 + qr;
        if ((lane & 3) == 0) { min1[row * 2 + wc] = b1; min2[row * 2 + wc] = b2; }
    }
    __syncthreads();

    if (tid < BM) {
        unsigned long long b1 = min1[tid * 2], b2 = min2[tid * 2];
        mrg2(b1, b2, min1[tid * 2 + 1], min2[tid * 2 + 1]);
        float amin = unford((uint32_t)(b1 >> 32));
        float d2nd = unford((uint32_t)(b2 >> 32));
        // margin = 2x rigorous fp16 screen bound (2^-10 ||r|| cmax) + absolute slop
        float cutv = amin + (1.0f / 512.0f) * sqrtf(rss[tid]) * g_cmax[stage] + 1e-3f;
        bestk[tid] = b1;
        need[tid]  = (d2nd <= cutv) ? 1 : 0;
    }
    __syncthreads();

    // ---- rescue: exact full 256-scan, 2 interleaved chains/lane, unrolled for MLP ----
    #pragma unroll 1
    for (int rr = 0; rr < 16; ++rr) {
        int lrow = wid * 16 + rr;
        if (!need[lrow]) continue;                      // warp-uniform
        int n = rowBase + lrow;
        const float4* xr = (const float4*)(x + (size_t)n * DD);
        const float4* pr = prev ? (const float4*)(prev + (size_t)n * DD) : nullptr;
        float rv = rss[lrow];
        unsigned long long bw = ~0ull;
        #pragma unroll 1
        for (int cc = 0; cc < 4; ++cc) {
            int kA = lane + 32 * (2 * cc);
            int kB = lane + 32 * (2 * cc + 1);
            const float4* crA = (const float4*)(C + (size_t)kA * DD);
            const float4* crB = (const float4*)(C + (size_t)kB * DD);
            float a = 0.f, b = 0.f;
            #pragma unroll 4
            for (int c2 = 0; c2 < 32; ++c2) {           // exact: d-ascending fmaf chains
                float4 xv = __ldg(xr + c2);
                float4 pv = pr ? __ldg(pr + c2) : make_float4(0.f, 0.f, 0.f, 0.f);
                float4 ca = __ldg(crA + c2);
                float4 cb4 = __ldg(crB + c2);
                float r0 = xv.x - pv.x, r1 = xv.y - pv.y;
                float r2 = xv.z - pv.z, r3 = xv.w - pv.w;
                a = fmaf(r0, ca.x, a);  b = fmaf(r0, cb4.x, b);
                a = fmaf(r1, ca.y, a);  b = fmaf(r1, cb4.y, b);
                a = fmaf(r2, ca.z, a);  b = fmaf(r2, cb4.z, b);
                a = fmaf(r3, ca.w, a);  b = fmaf(r3, cb4.w, b);
            }
            float d2A = __fadd_rn(__fadd_rn(rv, __fmul_rn(-2.0f, a)), csq[kA]);
            float d2B = __fadd_rn(__fadd_rn(rv, __fmul_rn(-2.0f, b)), csq[kB]);
            unsigned long long pA = ((unsigned long long)ford(d2A) << 32) | (unsigned)kA;
            unsigned long long pB = ((unsigned long long)ford(d2B) << 32) | (unsigned)kB;
            if (pA < bw) bw = pA;
            if (pB < bw) bw = pB;
        }
        #pragma unroll
        for (int off = 16; off > 0; off >>= 1) {
            unsigned long long o = __shfl_xor_sync(0xffffffffu, bw, off);
            if (o < bw) bw = o;
        }
        if (lane == 0) bestk[lrow] = bw;
    }
    __syncwarp();

    // ---- outputs: one-hot codes + recon (bit-exact recurrence), float4 stores ----
    #pragma unroll 1
    for (int rr = 0; rr < 16; ++rr) {
        int lrow = wid * 16 + rr;
        int n    = rowBase + lrow;
        int bidx = (int)(bestk[lrow] & 0xffffffffull);

        float4* crow = (float4*)(codes + (size_t)n * (MM * KK) + (size_t)stage * KK);
        #pragma unroll
        for (int t = 0; t < 2; ++t) {
            int j  = lane + 32 * t;
            int k0 = j * 4;
            float4 v;
            v.x = (k0     == bidx) ? 1.0f : 0.0f;
            v.y = (k0 + 1 == bidx) ? 1.0f : 0.0f;
            v.z = (k0 + 2 == bidx) ? 1.0f : 0.0f;
            v.w = (k0 + 3 == bidx) ? 1.0f : 0.0f;
            crow[j] = v;
        }
        float4 cv = __ldg((const float4*)(C + (size_t)bidx * DD) + lane);
        float4 pp = prev ? __ldg((const float4*)(prev + (size_t)n * DD) + lane)
                         : make_float4(0.f, 0.f, 0.f, 0.f);
        float4 v;
        v.x = __fadd_rn(pp.x, cv.x);
        v.y = __fadd_rn(pp.y, cv.y);
        v.z = __fadd_rn(pp.z, cv.z);
        v.w = __fadd_rn(pp.w, cv.w);
        ((float4*)(sideStage + (size_t)n * DD))[lane] = v;
        if (last) ((float4*)(xrecon + (size_t)n * DD))[lane] = v;
    }
}

extern "C" void kernel_launch(void* const* d_in, const int* in_sizes, int n_in,
                              void* d_out, int out_size)
{
    (void)in_sizes; (void)n_in; (void)out_size;
    const float* x  = (const float*)d_in[0];            // (N, D)
    const float* cb = (const float*)d_in[1];            // (M, K, D)

    float* out    = (float*)d_out;
    float* xrecon = out;                                // (N, D)
    float* codes  = out + (size_t)NN * DD;              // (N, M, K)
    float* side   = codes + (size_t)NN * MM * KK;       // (M, N, D)

    cudaFuncSetAttribute(rq_stage_kernel,
                         cudaFuncAttributeMaxDynamicSharedMemorySize, SM_BYTES);

    csq_prep_kernel<<<MM, KK>>>(cb);

    const int grid = NN / BM;   // 512
    for (int i = 0; i < MM; ++i) {
        const float* prev = (i == 0) ? nullptr : (side + (size_t)(i - 1) * NN * DD);
        rq_stage_kernel<<<grid, THREADS, SM_BYTES>>>(
            x, cb + (size_t)i * KK * DD, prev, codes,
            side + (size_t)i * NN * DD, xrecon, i, i == MM - 1);
    }
}

// round 12
// speedup vs baseline: 2.1236x; 1.7449x over previous
#include <cuda_runtime.h>
#include <cuda_fp16.h>
#include <cstdint>
#include <cfloat>

// Problem constants
#define NN 65536
#define DD 128
#define MM 8
#define KK 256

#define BM      128
#define THREADS 256            // 8 warps: wr = wid&3 (32-row group), wc = wid>>2 (128-col strip)

// fp16 tile row stride: 136 elems = 272B; 272 % 128 = 16 -> ldmatrix conflict-free
#define ROWB 272

// smem layout (byte offsets)
#define SM_CB    0                       // 256*272 = 69632
#define SM_RB    69632                   // 128*272 = 34816
#define SM_CSQ   104448                  // 1024
#define SM_RSS   105472                  // 512
#define SM_MIN1  105984                  // 128*2*8 = 2048
#define SM_MIN2  108032                  // 2048
#define SM_BESTK 110080                  // 128*8 = 1024
#define SM_NEED  111104                  // 128*4 = 512
#define SM_BYTES 111616                  // 109.0 KB -> 2 CTAs/SM

__device__ float g_csq[MM][KK];
__device__ float g_cmax[MM];
// transposed fp32 codebooks: g_cbT[st][d][k] (1MB, L2-resident) -> coalesced rescue
__device__ float g_cbT[(size_t)MM * DD * KK];

__device__ __forceinline__ uint32_t ford(float f) {
    uint32_t u = __float_as_uint(f);
    return (u & 0x80000000u) ? ~u : (u | 0x80000000u);
}
__device__ __forceinline__ float unford(uint32_t e) {
    return __uint_as_float((e & 0x80000000u) ? (e & 0x7fffffffu) : ~e);
}
__device__ __forceinline__ uint32_t smem_u32(const void* p) {
    uint32_t a;
    asm("{ .reg .u64 t; cvta.to.shared.u64 t, %1; cvt.u32.u64 %0, t; }" : "=r"(a) : "l"(p));
    return a;
}
__device__ __forceinline__ void ldm_x4(uint32_t& r0, uint32_t& r1, uint32_t& r2,
                                       uint32_t& r3, uint32_t addr) {
    asm volatile("ldmatrix.sync.aligned.m8n8.x4.shared.b16 {%0,%1,%2,%3}, [%4];"
                 : "=r"(r0), "=r"(r1), "=r"(r2), "=r"(r3) : "r"(addr));
}
__device__ __forceinline__ void mma_f16(float& c0, float& c1, float& c2, float& c3,
                                        uint32_t a0, uint32_t a1, uint32_t a2, uint32_t a3,
                                        uint32_t b0, uint32_t b1) {
    asm volatile("mma.sync.aligned.m16n8k16.row.col.f32.f16.f16.f32 "
                 "{%0,%1,%2,%3}, {%4,%5,%6,%7}, {%8,%9}, {%0,%1,%2,%3};"
                 : "+f"(c0), "+f"(c1), "+f"(c2), "+f"(c3)
                 : "r"(a0), "r"(a1), "r"(a2), "r"(a3), "r"(b0), "r"(b1));
}
__device__ __forceinline__ void upd2(unsigned long long& b1, unsigned long long& b2,
                                     unsigned long long k) {
    if (k < b1) { b2 = b1; b1 = k; }
    else if (k < b2) b2 = k;
}
__device__ __forceinline__ void mrg2(unsigned long long& b1, unsigned long long& b2,
                                     unsigned long long o1, unsigned long long o2) {
    if (o1 < b1) { b2 = (b1 < o2) ? b1 : o2; b1 = o1; }
    else         { b2 = (b2 < o1) ? b2 : o1; }
}

__global__ void csq_prep_kernel(const float* __restrict__ cb) {
    int st = blockIdx.x;
    int k  = threadIdx.x;                  // 256 threads
    const float* row = cb + ((size_t)st * KK + k) * DD;
    float s = 0.f;
    for (int d = 0; d < DD; ++d) { float v = row[d]; s = fmaf(v, v, s); }
    g_csq[st][k] = s;
    __shared__ float red[KK];
    red[k] = s;
    __syncthreads();
    for (int off = 128; off > 0; off >>= 1) {
        if (k < off) red[k] = fmaxf(red[k], red[k + off]);
        __syncthreads();
    }
    if (k == 0) g_cmax[st] = sqrtf(red[0]);
}

// one-shot transpose: g_cbT[st][d][k] = cb[st][k][d]
__global__ void cbt_prep_kernel(const float* __restrict__ cb) {
    int st = blockIdx.x, d = blockIdx.y;
    int k  = threadIdx.x;                  // 256 threads
    g_cbT[((size_t)st * DD + d) * KK + k] = cb[((size_t)st * KK + k) * DD + d];
}

__global__ __launch_bounds__(THREADS, 2)
void rq_stage_kernel(const float* __restrict__ x,
                     const float* __restrict__ C,       // stage codebook (K, D) fp32
                     const float* __restrict__ prev,    // side[stage-1] or null
                     float* __restrict__ codes,
                     float* __restrict__ sideStage,
                     float* __restrict__ xrecon,
                     int stage, int last)
{
    extern __shared__ char smem[];
    const uint32_t sbase = smem_u32(smem);
    float* csq = (float*)(smem + SM_CSQ);
    float* rss = (float*)(smem + SM_RSS);
    unsigned long long* min1  = (unsigned long long*)(smem + SM_MIN1);
    unsigned long long* min2  = (unsigned long long*)(smem + SM_MIN2);
    unsigned long long* bestk = (unsigned long long*)(smem + SM_BESTK);
    int* need = (int*)(smem + SM_NEED);

    const int tid  = threadIdx.x;
    const int wid  = tid >> 5;
    const int lane = tid & 31;
    const int rowBase = blockIdx.x * BM;

    // ---- codebook fp32 -> fp16 smem tile (float4 loads for MLP) ----
    #pragma unroll 4
    for (int j = 0; j < (KK * DD / 4) / THREADS; ++j) {   // 32 float4s/thread
        int idx4 = tid + j * THREADS;
        int k = idx4 >> 5, dq = idx4 & 31;                // 32 float4 per row
        float4 v = *(const float4*)(C + (size_t)k * DD + dq * 4);
        __half2 h0 = __floats2half2_rn(v.x, v.y);
        __half2 h1 = __floats2half2_rn(v.z, v.w);
        uint2 pk = make_uint2(*(uint32_t*)&h0, *(uint32_t*)&h1);
        *(uint2*)(smem + SM_CB + k * ROWB + dq * 8) = pk;
    }
    if (tid < KK) csq[tid] = g_csq[stage][tid];

    // ---- residual -> fp16 tile + exact fp32 rss ----
    {
        int r  = tid >> 1;
        int c0 = (tid & 1) * 64;
        const float* xrow = x + (size_t)(rowBase + r) * DD + c0;
        const float* prow = prev ? prev + (size_t)(rowBase + r) * DD + c0 : nullptr;
        float part = 0.f;
        #pragma unroll 4
        for (int j = 0; j < 64; j += 4) {
            float4 xv = *(const float4*)(xrow + j);
            float4 pv = prow ? *(const float4*)(prow + j) : make_float4(0.f,0.f,0.f,0.f);
            float r0 = xv.x - pv.x, r1 = xv.y - pv.y;
            float r2 = xv.z - pv.z, r3 = xv.w - pv.w;
            __half2 h0 = __floats2half2_rn(r0, r1);
            __half2 h1 = __floats2half2_rn(r2, r3);
            uint2 pk = make_uint2(*(uint32_t*)&h0, *(uint32_t*)&h1);
            *(uint2*)(smem + SM_RB + r * ROWB + (c0 + j) * 2) = pk;
            part = fmaf(r0, r0, part); part = fmaf(r1, r1, part);
            part = fmaf(r2, r2, part); part = fmaf(r3, r3, part);
        }
        part += __shfl_xor_sync(0xffffffffu, part, 1);
        if ((tid & 1) == 0) rss[r] = part;
    }
    __syncthreads();

    const int wr = wid & 3;
    const int wc = wid >> 2;                // 0..1: 128-col strip
    const int m_base  = wr * 32;
    const int n_base0 = wc * 128;
    const int qr = lane >> 2;
    const int qc = (lane & 3) * 2;

    // ldmatrix lane address offsets (bytes within a tile)
    const uint32_t aOff = (uint32_t)(((lane & 7) + ((lane >> 3) & 1) * 8 + m_base) * ROWB
                                     + ((lane >> 4) & 1) * 16);
    const uint32_t bOff = (uint32_t)(((lane & 7) + ((lane >> 4) & 1) * 8) * ROWB
                                     + ((lane >> 3) & 1) * 16);
    const uint32_t rbT = sbase + SM_RB, cbT = sbase + SM_CB;

    unsigned long long bk1[4], bk2[4];
    #pragma unroll
    for (int i = 0; i < 4; ++i) { bk1[i] = ~0ull; bk2[i] = ~0ull; }

    // ---- single fp16 GEMM pass, 16-col chunks; fold (best,second) per row-slot ----
    #pragma unroll 1
    for (int ch = 0; ch < 8; ++ch) {
        const int n_base = n_base0 + ch * 16;
        const uint32_t bCh = bOff + (uint32_t)n_base * ROWB;
        float acc[2][2][4];
        #pragma unroll
        for (int mt = 0; mt < 2; ++mt)
            #pragma unroll
            for (int nt = 0; nt < 2; ++nt)
                #pragma unroll
                for (int c = 0; c < 4; ++c) acc[mt][nt][c] = 0.f;

        #pragma unroll 2
        for (int ks = 0; ks < 8; ++ks) {
            const uint32_t k2 = (uint32_t)ks * 32;   // 16 fp16 = 32 bytes
            uint32_t a0[4], a1[4], b[4];
            ldm_x4(a0[0], a0[1], a0[2], a0[3], rbT + aOff + k2);
            ldm_x4(a1[0], a1[1], a1[2], a1[3], rbT + aOff + k2 + 16 * ROWB);
            ldm_x4(b[0],  b[1],  b[2],  b[3],  cbT + bCh + k2);
            mma_f16(acc[0][0][0], acc[0][0][1], acc[0][0][2], acc[0][0][3],
                    a0[0], a0[1], a0[2], a0[3], b[0], b[1]);
            mma_f16(acc[0][1][0], acc[0][1][1], acc[0][1][2], acc[0][1][3],
                    a0[0], a0[1], a0[2], a0[3], b[2], b[3]);
            mma_f16(acc[1][0][0], acc[1][0][1], acc[1][0][2], acc[1][0][3],
                    a1[0], a1[1], a1[2], a1[3], b[0], b[1]);
            mma_f16(acc[1][1][0], acc[1][1][1], acc[1][1][2], acc[1][1][3],
                    a1[0], a1[1], a1[2], a1[3], b[2], b[3]);
        }
        #pragma unroll
        for (int mt = 0; mt < 2; ++mt)
            #pragma unroll
            for (int h = 0; h < 2; ++h) {
                int row = m_base + mt * 16 + h * 8 + qr;
                float rv = rss[row];
                int sl = mt * 2 + h;
                #pragma unroll
                for (int nt = 0; nt < 2; ++nt)
                    #pragma unroll
                    for (int p = 0; p < 2; ++p) {
                        int k = n_base + nt * 8 + qc + p;
                        float d2 = __fadd_rn(
                            __fadd_rn(rv, __fmul_rn(-2.f, acc[mt][nt][h * 2 + p])), csq[k]);
                        upd2(bk1[sl], bk2[sl],
                             ((unsigned long long)ford(d2) << 32) | (unsigned)k);
                    }
            }
    }
    // quad-reduce, publish per-(row, strip) best/second
    #pragma unroll
    for (int i = 0; i < 4; ++i) {
        unsigned long long b1 = bk1[i], b2 = bk2[i];
        mrg2(b1, b2, __shfl_xor_sync(0xffffffffu, b1, 1), __shfl_xor_sync(0xffffffffu, b2, 1));
        mrg2(b1, b2, __shfl_xor_sync(0xffffffffu, b1, 2), __shfl_xor_sync(0xffffffffu, b2, 2));
        int row = m_base + (i >> 1) * 16 + (i & 1) * 8 + qr;
        if ((lane & 3) == 0) { min1[row * 2 + wc] = b1; min2[row * 2 + wc] = b2; }
    }
    __syncthreads();

    if (tid < BM) {
        unsigned long long b1 = min1[tid * 2], b2 = min2[tid * 2];
        mrg2(b1, b2, min1[tid * 2 + 1], min2[tid * 2 + 1]);
        float amin = unford((uint32_t)(b1 >> 32));
        float d2nd = unford((uint32_t)(b2 >> 32));
        // margin = rigorous fp16 screen bound (2^-9 ||r|| cmax) + absolute slop (validated)
        float cutv = amin + (1.0f / 512.0f) * sqrtf(rss[tid]) * g_cmax[stage] + 1e-3f;
        bestk[tid] = b1;
        need[tid]  = (d2nd <= cutv) ? 1 : 0;
    }
    __syncthreads();

    // ---- rescue: exact full 256-scan via TRANSPOSED codebook (coalesced) ----
    // lane owns k = lane*8 + j (j=0..7); per d, lanes load 512B contiguous from cbT.
    // Per-codeword chain: d-ascending fmaf into scalar acc — identical semantics
    // to all prior passing rounds (same floats, same order).
    const float* ctT = g_cbT + (size_t)stage * DD * KK;
    #pragma unroll 1
    for (int rr = 0; rr < 16; ++rr) {
        int lrow = wid * 16 + rr;
        if (!need[lrow]) continue;                      // warp-uniform
        int n = rowBase + lrow;
        const float4* xr = (const float4*)(x + (size_t)n * DD);
        const float4* pr = prev ? (const float4*)(prev + (size_t)n * DD) : nullptr;
        float rv = rss[lrow];
        const int kbase = lane * 8;
        float a[8];
        #pragma unroll
        for (int j = 0; j < 8; ++j) a[j] = 0.f;
        #pragma unroll 2
        for (int c2 = 0; c2 < 32; ++c2) {
            float4 xv = __ldg(xr + c2);
            float4 pv = pr ? __ldg(pr + c2) : make_float4(0.f, 0.f, 0.f, 0.f);
            float rd[4];
            rd[0] = xv.x - pv.x; rd[1] = xv.y - pv.y;
            rd[2] = xv.z - pv.z; rd[3] = xv.w - pv.w;
            #pragma unroll
            for (int q = 0; q < 4; ++q) {
                const int d = c2 * 4 + q;
                const float4* crow = (const float4*)(ctT + (size_t)d * KK + kbase);
                float4 c0 = __ldg(crow);
                float4 c1 = __ldg(crow + 1);
                a[0] = fmaf(rd[q], c0.x, a[0]);
                a[1] = fmaf(rd[q], c0.y, a[1]);
                a[2] = fmaf(rd[q], c0.z, a[2]);
                a[3] = fmaf(rd[q], c0.w, a[3]);
                a[4] = fmaf(rd[q], c1.x, a[4]);
                a[5] = fmaf(rd[q], c1.y, a[5]);
                a[6] = fmaf(rd[q], c1.z, a[6]);
                a[7] = fmaf(rd[q], c1.w, a[7]);
            }
        }
        unsigned long long bw = ~0ull;
        #pragma unroll
        for (int j = 0; j < 8; ++j) {
            int k = kbase + j;
            float d2e = __fadd_rn(__fadd_rn(rv, __fmul_rn(-2.0f, a[j])), csq[k]);
            unsigned long long pk = ((unsigned long long)ford(d2e) << 32) | (unsigned)k;
            if (pk < bw) bw = pk;
        }
        #pragma unroll
        for (int off = 16; off > 0; off >>= 1) {
            unsigned long long o = __shfl_xor_sync(0xffffffffu, bw, off);
            if (o < bw) bw = o;
        }
        if (lane == 0) bestk[lrow] = bw;
    }
    __syncwarp();

    // ---- outputs: one-hot codes + recon (bit-exact recurrence), float4 stores ----
    #pragma unroll 1
    for (int rr = 0; rr < 16; ++rr) {
        int lrow = wid * 16 + rr;
        int n    = rowBase + lrow;
        int bidx = (int)(bestk[lrow] & 0xffffffffull);

        float4* crow = (float4*)(codes + (size_t)n * (MM * KK) + (size_t)stage * KK);
        #pragma unroll
        for (int t = 0; t < 2; ++t) {
            int j  = lane + 32 * t;
            int k0 = j * 4;
            float4 v;
            v.x = (k0     == bidx) ? 1.0f : 0.0f;
            v.y = (k0 + 1 == bidx) ? 1.0f : 0.0f;
            v.z = (k0 + 2 == bidx) ? 1.0f : 0.0f;
            v.w = (k0 + 3 == bidx) ? 1.0f : 0.0f;
            crow[j] = v;
        }
        float4 cv = __ldg((const float4*)(C + (size_t)bidx * DD) + lane);
        float4 pp = prev ? __ldg((const float4*)(prev + (size_t)n * DD) + lane)
                         : make_float4(0.f, 0.f, 0.f, 0.f);
        float4 v;
        v.x = __fadd_rn(pp.x, cv.x);
        v.y = __fadd_rn(pp.y, cv.y);
        v.z = __fadd_rn(pp.z, cv.z);
        v.w = __fadd_rn(pp.w, cv.w);
        ((float4*)(sideStage + (size_t)n * DD))[lane] = v;
        if (last) ((float4*)(xrecon + (size_t)n * DD))[lane] = v;
    }
}

extern "C" void kernel_launch(void* const* d_in, const int* in_sizes, int n_in,
                              void* d_out, int out_size)
{
    (void)in_sizes; (void)n_in; (void)out_size;
    const float* x  = (const float*)d_in[0];            // (N, D)
    const float* cb = (const float*)d_in[1];            // (M, K, D)

    float* out    = (float*)d_out;
    float* xrecon = out;                                // (N, D)
    float* codes  = out + (size_t)NN * DD;              // (N, M, K)
    float* side   = codes + (size_t)NN * MM * KK;       // (M, N, D)

    cudaFuncSetAttribute(rq_stage_kernel,
                         cudaFuncAttributeMaxDynamicSharedMemorySize, SM_BYTES);

    csq_prep_kernel<<<MM, KK>>>(cb);
    cbt_prep_kernel<<<dim3(MM, DD), KK>>>(cb);

    const int grid = NN / BM;   // 512
    for (int i = 0; i < MM; ++i) {
        const float* prev = (i == 0) ? nullptr : (side + (size_t)(i - 1) * NN * DD);
        rq_stage_kernel<<<grid, THREADS, SM_BYTES>>>(
            x, cb + (size_t)i * KK * DD, prev, codes,
            side + (size_t)i * NN * DD, xrecon, i, i == MM - 1);
    }
}

// round 13
// speedup vs baseline: 2.2270x; 1.0487x over previous
#include <cuda_runtime.h>
#include <cuda_fp16.h>
#include <cstdint>
#include <cfloat>

// Problem constants
#define NN 65536
#define DD 128
#define MM 8
#define KK 256

#define BM      128
#define THREADS 256            // 8 warps: wr = wid&3 (32-row group), wc = wid>>2 (128-col strip)

// fp16 tile row stride: 136 elems = 272B; 272 % 128 = 16 -> ldmatrix conflict-free
#define ROWB 272

// smem layout (byte offsets)
#define SM_CB    0                       // 256*272 = 69632
#define SM_RB    69632                   // 128*272 = 34816
#define SM_CSQ   104448                  // 1024
#define SM_RSS   105472                  // 512
#define SM_MIN1  105984                  // 128*2*8 = 2048
#define SM_MIN2  108032                  // 2048
#define SM_BESTK 110080                  // 128*8 = 1024
#define SM_NEED  111104                  // 128*4 = 512
#define SM_BYTES 111616                  // 109.0 KB -> 2 CTAs/SM

__device__ float g_csq[MM][KK];
__device__ float g_cmax[MM];
// transposed fp32 codebooks: g_cbT[st][d][k] (1MB, L2-resident) -> coalesced rescue
__device__ float g_cbT[(size_t)MM * DD * KK];
// fp16 codebook pre-packed in the exact padded smem image -> cp.async straight in
__device__ __align__(16) char g_cbH[MM][(size_t)KK * ROWB];

__device__ __forceinline__ uint32_t ford(float f) {
    uint32_t u = __float_as_uint(f);
    return (u & 0x80000000u) ? ~u : (u | 0x80000000u);
}
__device__ __forceinline__ float unford(uint32_t e) {
    return __uint_as_float((e & 0x80000000u) ? (e & 0x7fffffffu) : ~e);
}
__device__ __forceinline__ uint32_t smem_u32(const void* p) {
    uint32_t a;
    asm("{ .reg .u64 t; cvta.to.shared.u64 t, %1; cvt.u32.u64 %0, t; }" : "=r"(a) : "l"(p));
    return a;
}
__device__ __forceinline__ void cp_async16(uint32_t dst, const void* src) {
    asm volatile("cp.async.ca.shared.global [%0], [%1], 16;" :: "r"(dst), "l"(src));
}
__device__ __forceinline__ void cp_async_wait_all() {
    asm volatile("cp.async.commit_group;\n\tcp.async.wait_group 0;" ::: "memory");
}
__device__ __forceinline__ void ldm_x4(uint32_t& r0, uint32_t& r1, uint32_t& r2,
                                       uint32_t& r3, uint32_t addr) {
    asm volatile("ldmatrix.sync.aligned.m8n8.x4.shared.b16 {%0,%1,%2,%3}, [%4];"
                 : "=r"(r0), "=r"(r1), "=r"(r2), "=r"(r3) : "r"(addr));
}
__device__ __forceinline__ void mma_f16(float& c0, float& c1, float& c2, float& c3,
                                        uint32_t a0, uint32_t a1, uint32_t a2, uint32_t a3,
                                        uint32_t b0, uint32_t b1) {
    asm volatile("mma.sync.aligned.m16n8k16.row.col.f32.f16.f16.f32 "
                 "{%0,%1,%2,%3}, {%4,%5,%6,%7}, {%8,%9}, {%0,%1,%2,%3};"
                 : "+f"(c0), "+f"(c1), "+f"(c2), "+f"(c3)
                 : "r"(a0), "r"(a1), "r"(a2), "r"(a3), "r"(b0), "r"(b1));
}
__device__ __forceinline__ void upd2(unsigned long long& b1, unsigned long long& b2,
                                     unsigned long long k) {
    if (k < b1) { b2 = b1; b1 = k; }
    else if (k < b2) b2 = k;
}
__device__ __forceinline__ void mrg2(unsigned long long& b1, unsigned long long& b2,
                                     unsigned long long o1, unsigned long long o2) {
    if (o1 < b1) { b2 = (b1 < o2) ? b1 : o2; b1 = o1; }
    else         { b2 = (b2 < o1) ? b2 : o1; }
}

__global__ void csq_prep_kernel(const float* __restrict__ cb) {
    int st = blockIdx.x;
    int k  = threadIdx.x;                  // 256 threads
    const float* row = cb + ((size_t)st * KK + k) * DD;
    float s = 0.f;
    for (int d = 0; d < DD; ++d) { float v = row[d]; s = fmaf(v, v, s); }
    g_csq[st][k] = s;
    __shared__ float red[KK];
    red[k] = s;
    __syncthreads();
    for (int off = 128; off > 0; off >>= 1) {
        if (k < off) red[k] = fmaxf(red[k], red[k + off]);
        __syncthreads();
    }
    if (k == 0) g_cmax[st] = sqrtf(red[0]);
}

// one-shot transpose: g_cbT[st][d][k] = cb[st][k][d]
__global__ void cbt_prep_kernel(const float* __restrict__ cb) {
    int st = blockIdx.x, d = blockIdx.y;
    int k  = threadIdx.x;                  // 256 threads
    g_cbT[((size_t)st * DD + d) * KK + k] = cb[((size_t)st * KK + k) * DD + d];
}

// one-shot fp16 pack in padded smem image (row k at byte k*ROWB, padding zeroed)
__global__ void cbh_prep_kernel(const float* __restrict__ cb) {
    int st = blockIdx.x;
    int k  = threadIdx.x;                  // 256 threads, one codeword row each
    const float* row = cb + ((size_t)st * KK + k) * DD;
    char* dst = g_cbH[st] + (size_t)k * ROWB;
    for (int dp = 0; dp < 64; ++dp) {
        float2 v = *(const float2*)(row + dp * 2);
        __half2 h = __floats2half2_rn(v.x, v.y);
        *(uint32_t*)(dst + dp * 4) = *(uint32_t*)&h;
    }
    for (int j = 0; j < 4; ++j) *(uint32_t*)(dst + 256 + j * 4) = 0u;  // padding
}

// pre-zero the one-hot codes output (streaming stores, near DRAM peak)
__global__ void zero_codes_kernel(float4* __restrict__ p) {
    size_t i = (size_t)blockIdx.x * blockDim.x + threadIdx.x;
    const size_t n4 = (size_t)NN * MM * KK / 4;
    const size_t step = (size_t)gridDim.x * blockDim.x;
    float4 z = make_float4(0.f, 0.f, 0.f, 0.f);
    for (; i < n4; i += step) __stcs(p + i, z);
}

__global__ __launch_bounds__(THREADS, 2)
void rq_stage_kernel(const float* __restrict__ x,
                     const float* __restrict__ C,       // stage codebook (K, D) fp32
                     const float* __restrict__ prev,    // side[stage-1] or null
                     float* __restrict__ codes,
                     float* __restrict__ sideStage,
                     float* __restrict__ xrecon,
                     int stage, int last)
{
    extern __shared__ char smem[];
    const uint32_t sbase = smem_u32(smem);
    float* csq = (float*)(smem + SM_CSQ);
    float* rss = (float*)(smem + SM_RSS);
    unsigned long long* min1  = (unsigned long long*)(smem + SM_MIN1);
    unsigned long long* min2  = (unsigned long long*)(smem + SM_MIN2);
    unsigned long long* bestk = (unsigned long long*)(smem + SM_BESTK);
    int* need = (int*)(smem + SM_NEED);

    const int tid  = threadIdx.x;
    const int wid  = tid >> 5;
    const int lane = tid & 31;
    const int rowBase = blockIdx.x * BM;

    // ---- codebook fp16 tile via cp.async (overlaps with residual prep below) ----
    {
        const char* src = g_cbH[stage];
        #pragma unroll
        for (int j = 0; j < 17; ++j) {
            int c16 = tid + j * THREADS;        // 4352 chunks of 16B
            cp_async16(sbase + SM_CB + c16 * 16, src + (size_t)c16 * 16);
        }
    }
    if (tid < KK) csq[tid] = g_csq[stage][tid];

    // ---- residual -> fp16 tile + exact fp32 rss ----
    {
        int r  = tid >> 1;
        int c0 = (tid & 1) * 64;
        const float* xrow = x + (size_t)(rowBase + r) * DD + c0;
        const float* prow = prev ? prev + (size_t)(rowBase + r) * DD + c0 : nullptr;
        float part = 0.f;
        #pragma unroll 4
        for (int j = 0; j < 64; j += 4) {
            float4 xv = *(const float4*)(xrow + j);
            float4 pv = prow ? *(const float4*)(prow + j) : make_float4(0.f,0.f,0.f,0.f);
            float r0 = xv.x - pv.x, r1 = xv.y - pv.y;
            float r2 = xv.z - pv.z, r3 = xv.w - pv.w;
            __half2 h0 = __floats2half2_rn(r0, r1);
            __half2 h1 = __floats2half2_rn(r2, r3);
            uint2 pk = make_uint2(*(uint32_t*)&h0, *(uint32_t*)&h1);
            *(uint2*)(smem + SM_RB + r * ROWB + (c0 + j) * 2) = pk;
            part = fmaf(r0, r0, part); part = fmaf(r1, r1, part);
            part = fmaf(r2, r2, part); part = fmaf(r3, r3, part);
        }
        part += __shfl_xor_sync(0xffffffffu, part, 1);
        if ((tid & 1) == 0) rss[r] = part;
    }
    cp_async_wait_all();
    __syncthreads();

    const int wr = wid & 3;
    const int wc = wid >> 2;                // 0..1: 128-col strip
    const int m_base  = wr * 32;
    const int n_base0 = wc * 128;
    const int qr = lane >> 2;
    const int qc = (lane & 3) * 2;

    // ldmatrix lane address offsets (bytes within a tile)
    const uint32_t aOff = (uint32_t)(((lane & 7) + ((lane >> 3) & 1) * 8 + m_base) * ROWB
                                     + ((lane >> 4) & 1) * 16);
    const uint32_t bOff = (uint32_t)(((lane & 7) + ((lane >> 4) & 1) * 8) * ROWB
                                     + ((lane >> 3) & 1) * 16);
    const uint32_t rbT = sbase + SM_RB, cbT = sbase + SM_CB;

    unsigned long long bk1[4], bk2[4];
    #pragma unroll
    for (int i = 0; i < 4; ++i) { bk1[i] = ~0ull; bk2[i] = ~0ull; }

    // ---- single fp16 GEMM pass, 16-col chunks; fold (best,second) per row-slot ----
    #pragma unroll 1
    for (int ch = 0; ch < 8; ++ch) {
        const int n_base = n_base0 + ch * 16;
        const uint32_t bCh = bOff + (uint32_t)n_base * ROWB;
        float acc[2][2][4];
        #pragma unroll
        for (int mt = 0; mt < 2; ++mt)
            #pragma unroll
            for (int nt = 0; nt < 2; ++nt)
                #pragma unroll
                for (int c = 0; c < 4; ++c) acc[mt][nt][c] = 0.f;

        #pragma unroll 4
        for (int ks = 0; ks < 8; ++ks) {
            const uint32_t k2 = (uint32_t)ks * 32;   // 16 fp16 = 32 bytes
            uint32_t a0[4], a1[4], b[4];
            ldm_x4(a0[0], a0[1], a0[2], a0[3], rbT + aOff + k2);
            ldm_x4(a1[0], a1[1], a1[2], a1[3], rbT + aOff + k2 + 16 * ROWB);
            ldm_x4(b[0],  b[1],  b[2],  b[3],  cbT + bCh + k2);
            mma_f16(acc[0][0][0], acc[0][0][1], acc[0][0][2], acc[0][0][3],
                    a0[0], a0[1], a0[2], a0[3], b[0], b[1]);
            mma_f16(acc[0][1][0], acc[0][1][1], acc[0][1][2], acc[0][1][3],
                    a0[0], a0[1], a0[2], a0[3], b[2], b[3]);
            mma_f16(acc[1][0][0], acc[1][0][1], acc[1][0][2], acc[1][0][3],
                    a1[0], a1[1], a1[2], a1[3], b[0], b[1]);
            mma_f16(acc[1][1][0], acc[1][1][1], acc[1][1][2], acc[1][1][3],
                    a1[0], a1[1], a1[2], a1[3], b[2], b[3]);
        }
        #pragma unroll
        for (int mt = 0; mt < 2; ++mt)
            #pragma unroll
            for (int h = 0; h < 2; ++h) {
                int row = m_base + mt * 16 + h * 8 + qr;
                float rv = rss[row];
                int sl = mt * 2 + h;
                #pragma unroll
                for (int nt = 0; nt < 2; ++nt)
                    #pragma unroll
                    for (int p = 0; p < 2; ++p) {
                        int k = n_base + nt * 8 + qc + p;
                        float d2 = __fadd_rn(
                            __fadd_rn(rv, __fmul_rn(-2.f, acc[mt][nt][h * 2 + p])), csq[k]);
                        upd2(bk1[sl], bk2[sl],
                             ((unsigned long long)ford(d2) << 32) | (unsigned)k);
                    }
            }
    }
    // quad-reduce, publish per-(row, strip) best/second
    #pragma unroll
    for (int i = 0; i < 4; ++i) {
        unsigned long long b1 = bk1[i], b2 = bk2[i];
        mrg2(b1, b2, __shfl_xor_sync(0xffffffffu, b1, 1), __shfl_xor_sync(0xffffffffu, b2, 1));
        mrg2(b1, b2, __shfl_xor_sync(0xffffffffu, b1, 2), __shfl_xor_sync(0xffffffffu, b2, 2));
        int row = m_base + (i >> 1) * 16 + (i & 1) * 8 + qr;
        if ((lane & 3) == 0) { min1[row * 2 + wc] = b1; min2[row * 2 + wc] = b2; }
    }
    __syncthreads();

    if (tid < BM) {
        unsigned long long b1 = min1[tid * 2], b2 = min2[tid * 2];
        mrg2(b1, b2, min1[tid * 2 + 1], min2[tid * 2 + 1]);
        float amin = unford((uint32_t)(b1 >> 32));
        float d2nd = unford((uint32_t)(b2 >> 32));
        // margin = rigorous fp16 screen bound (2^-9 ||r|| cmax) + absolute slop (validated)
        float cutv = amin + (1.0f / 512.0f) * sqrtf(rss[tid]) * g_cmax[stage] + 1e-3f;
        bestk[tid] = b1;
        need[tid]  = (d2nd <= cutv) ? 1 : 0;
    }
    __syncthreads();

    // ---- rescue: exact full 256-scan via TRANSPOSED codebook (coalesced) ----
    const float* ctT = g_cbT + (size_t)stage * DD * KK;
    #pragma unroll 1
    for (int rr = 0; rr < 16; ++rr) {
        int lrow = wid * 16 + rr;
        if (!need[lrow]) continue;                      // warp-uniform
        int n = rowBase + lrow;
        const float4* xr = (const float4*)(x + (size_t)n * DD);
        const float4* pr = prev ? (const float4*)(prev + (size_t)n * DD) : nullptr;
        float rv = rss[lrow];
        const int kbase = lane * 8;
        float a[8];
        #pragma unroll
        for (int j = 0; j < 8; ++j) a[j] = 0.f;
        #pragma unroll 2
        for (int c2 = 0; c2 < 32; ++c2) {
            float4 xv = __ldg(xr + c2);
            float4 pv = pr ? __ldg(pr + c2) : make_float4(0.f, 0.f, 0.f, 0.f);
            float rd[4];
            rd[0] = xv.x - pv.x; rd[1] = xv.y - pv.y;
            rd[2] = xv.z - pv.z; rd[3] = xv.w - pv.w;
            #pragma unroll
            for (int q = 0; q < 4; ++q) {
                const int d = c2 * 4 + q;
                const float4* crow = (const float4*)(ctT + (size_t)d * KK + kbase);
                float4 c0 = __ldg(crow);
                float4 c1 = __ldg(crow + 1);
                a[0] = fmaf(rd[q], c0.x, a[0]);
                a[1] = fmaf(rd[q], c0.y, a[1]);
                a[2] = fmaf(rd[q], c0.z, a[2]);
                a[3] = fmaf(rd[q], c0.w, a[3]);
                a[4] = fmaf(rd[q], c1.x, a[4]);
                a[5] = fmaf(rd[q], c1.y, a[5]);
                a[6] = fmaf(rd[q], c1.z, a[6]);
                a[7] = fmaf(rd[q], c1.w, a[7]);
            }
        }
        unsigned long long bw = ~0ull;
        #pragma unroll
        for (int j = 0; j < 8; ++j) {
            int k = kbase + j;
            float d2e = __fadd_rn(__fadd_rn(rv, __fmul_rn(-2.0f, a[j])), csq[k]);
            unsigned long long pk = ((unsigned long long)ford(d2e) << 32) | (unsigned)k;
            if (pk < bw) bw = pk;
        }
        #pragma unroll
        for (int off = 16; off > 0; off >>= 1) {
            unsigned long long o = __shfl_xor_sync(0xffffffffu, bw, off);
            if (o < bw) bw = o;
        }
        if (lane == 0) bestk[lrow] = bw;
    }
    __syncwarp();

    // ---- outputs: single 1.0 into pre-zeroed codes + recon (bit-exact recurrence) ----
    #pragma unroll 1
    for (int rr = 0; rr < 16; ++rr) {
        int lrow = wid * 16 + rr;
        int n    = rowBase + lrow;
        int bidx = (int)(bestk[lrow] & 0xffffffffull);

        if (lane == 0)
            codes[(size_t)n * (MM * KK) + (size_t)stage * KK + bidx] = 1.0f;

        float4 cv = __ldg((const float4*)(C + (size_t)bidx * DD) + lane);
        float4 pp = prev ? __ldg((const float4*)(prev + (size_t)n * DD) + lane)
                         : make_float4(0.f, 0.f, 0.f, 0.f);
        float4 v;
        v.x = __fadd_rn(pp.x, cv.x);
        v.y = __fadd_rn(pp.y, cv.y);
        v.z = __fadd_rn(pp.z, cv.z);
        v.w = __fadd_rn(pp.w, cv.w);
        ((float4*)(sideStage + (size_t)n * DD))[lane] = v;
        if (last) ((float4*)(xrecon + (size_t)n * DD))[lane] = v;
    }
}

extern "C" void kernel_launch(void* const* d_in, const int* in_sizes, int n_in,
                              void* d_out, int out_size)
{
    (void)in_sizes; (void)n_in; (void)out_size;
    const float* x  = (const float*)d_in[0];            // (N, D)
    const float* cb = (const float*)d_in[1];            // (M, K, D)

    float* out    = (float*)d_out;
    float* xrecon = out;                                // (N, D)
    float* codes  = out + (size_t)NN * DD;              // (N, M, K)
    float* side   = codes + (size_t)NN * MM * KK;       // (M, N, D)

    cudaFuncSetAttribute(rq_stage_kernel,
                         cudaFuncAttributeMaxDynamicSharedMemorySize, SM_BYTES);

    csq_prep_kernel<<<MM, KK>>>(cb);
    cbt_prep_kernel<<<dim3(MM, DD), KK>>>(cb);
    cbh_prep_kernel<<<MM, KK>>>(cb);
    zero_codes_kernel<<<4096, 256>>>((float4*)codes);

    const int grid = NN / BM;   // 512
    for (int i = 0; i < MM; ++i) {
        const float* prev = (i == 0) ? nullptr : (side + (size_t)(i - 1) * NN * DD);
        rq_stage_kernel<<<grid, THREADS, SM_BYTES>>>(
            x, cb + (size_t)i * KK * DD, prev, codes,
            side + (size_t)i * NN * DD, xrecon, i, i == MM - 1);
    }
}